// round 1
// baseline (speedup 1.0000x reference)
#include <cuda_runtime.h>

#define FULL 0xffffffffu
constexpr int NW = 10;   // wires
constexpr int NL = 4;    // layers

// Per Rot gate: 2 x float4 = (U00.re,U00.im,U01.re,U01.im), (U10.re,U10.im,U11.re,U11.im)
__device__ float4 g_rot[NL * NW * 2];

// ---------------------------------------------------------------------------
// Prep: build the 40 Rot matrices from weights (shared across all samples)
// qml.Rot(phi, theta, omega) = RZ(omega) RY(theta) RZ(phi)
// ---------------------------------------------------------------------------
__global__ void prep_kernel(const float* __restrict__ w) {
    int g = blockIdx.x * blockDim.x + threadIdx.x;
    if (g >= NL * NW) return;
    float phi = w[g * 3 + 0], th = w[g * 3 + 1], om = w[g * 3 + 2];
    float sth, cth;
    sincosf(0.5f * th, &sth, &cth);
    float sp, cp;  // e^{-i(phi+om)/2} = cp + i*sp
    sincosf(-0.5f * (phi + om), &sp, &cp);
    float sm, cm;  // e^{+i(phi-om)/2} = cm + i*sm
    sincosf(0.5f * (phi - om), &sm, &cm);
    // m00 = e^{-i(phi+om)/2} c ; m01 = -e^{i(phi-om)/2} s
    // m10 = e^{-i(phi-om)/2} s ; m11 = e^{+i(phi+om)/2} c
    g_rot[g * 2 + 0] = make_float4(cp * cth, sp * cth, -cm * sth, -sm * sth);
    g_rot[g * 2 + 1] = make_float4(cm * sth, -sm * sth, cp * cth, -sp * cth);
}

// ---------------------------------------------------------------------------
// Helpers
// ---------------------------------------------------------------------------
__device__ __forceinline__ float2 shx2(float2 v, int mask) {
    float2 r;
    r.x = __shfl_xor_sync(FULL, v.x, mask);
    r.y = __shfl_xor_sync(FULL, v.y, mask);
    return r;
}
__device__ __forceinline__ float2 shidx2(float2 v, int src) {
    float2 r;
    r.x = __shfl_sync(FULL, v.x, src);
    r.y = __shfl_sync(FULL, v.y, src);
    return r;
}
__device__ __forceinline__ float2 cmul(float2 u, float2 a) {
    return make_float2(u.x * a.x - u.y * a.y, u.x * a.y + u.y * a.x);
}
__device__ __forceinline__ float2 cmadd(float2 u, float2 a, float2 acc) {
    acc.x = fmaf(u.x, a.x, fmaf(-u.y, a.y, acc.x));
    acc.y = fmaf(u.x, a.y, fmaf(u.y, a.x, acc.y));
    return acc;
}

// ---------------------------------------------------------------------------
// Gates. Index bit for wire W is p = 9 - W. Bits 9..5 = lane bits (lane bit
// p-5), bits 4..0 = local register bits.
// ---------------------------------------------------------------------------
template <int W>
__device__ __forceinline__ void rotGate(float2 st[32], int lane, int gidx) {
    float4 g0 = g_rot[gidx * 2 + 0];
    float4 g1 = g_rot[gidx * 2 + 1];
    float2 U00 = make_float2(g0.x, g0.y), U01 = make_float2(g0.z, g0.w);
    float2 U10 = make_float2(g1.x, g1.y), U11 = make_float2(g1.z, g1.w);
    constexpr int p = 9 - W;
    if constexpr (p >= 5) {
        constexpr int lb = p - 5;
        int bit = (lane >> lb) & 1;
        float2 co = bit ? U11 : U00;  // coeff for own amplitude
        float2 ct = bit ? U10 : U01;  // coeff for partner amplitude
#pragma unroll
        for (int m = 0; m < 32; ++m) {
            float2 own = st[m];
            float2 oth = shx2(own, 1 << lb);
            st[m] = cmadd(ct, oth, cmul(co, own));
        }
    } else {
        constexpr int bm = 1 << p;
#pragma unroll
        for (int m = 0; m < 32; ++m) {
            if (!(m & bm)) {
                float2 a0 = st[m], a1 = st[m | bm];
                st[m]      = cmadd(U01, a1, cmul(U00, a0));
                st[m | bm] = cmadd(U11, a1, cmul(U10, a0));
            }
        }
    }
}

template <int W>
__device__ __forceinline__ void ryGate(float2 st[32], int lane, float c, float s) {
    constexpr int p = 9 - W;
    if constexpr (p >= 5) {
        constexpr int lb = p - 5;
        int bit = (lane >> lb) & 1;
        float sg = bit ? s : -s;  // new = c*own + sg*other
#pragma unroll
        for (int m = 0; m < 32; ++m) {
            float2 own = st[m];
            float2 oth = shx2(own, 1 << lb);
            st[m] = make_float2(fmaf(c, own.x, sg * oth.x),
                                fmaf(c, own.y, sg * oth.y));
        }
    } else {
        constexpr int bm = 1 << p;
#pragma unroll
        for (int m = 0; m < 32; ++m) {
            if (!(m & bm)) {
                float2 a0 = st[m], a1 = st[m | bm];
                st[m]      = make_float2(fmaf(c, a0.x, -s * a1.x),
                                         fmaf(c, a0.y, -s * a1.y));
                st[m | bm] = make_float2(fmaf(s, a0.x, c * a1.x),
                                         fmaf(s, a0.y, c * a1.y));
            }
        }
    }
}

template <int CW, int TW>
__device__ __forceinline__ void cnotGate(float2 st[32], int lane) {
    constexpr int pc = 9 - CW, pt = 9 - TW;
    if constexpr (pc < 5 && pt < 5) {
        // local control, local target: register swap
        constexpr int cm = 1 << pc, tm = 1 << pt;
#pragma unroll
        for (int m = 0; m < 32; ++m) {
            if ((m & cm) && !(m & tm)) {
                float2 a = st[m];
                st[m] = st[m | tm];
                st[m | tm] = a;
            }
        }
    } else if constexpr (pc < 5 && pt >= 5) {
        // local control, lane target: cross-lane swap for locals with c=1
        constexpr int cm = 1 << pc, tlm = 1 << (pt - 5);
#pragma unroll
        for (int m = 0; m < 32; ++m) {
            if (m & cm) st[m] = shx2(st[m], tlm);
        }
    } else if constexpr (pc >= 5 && pt < 5) {
        // lane control, local target: predicated register swap
        constexpr int tm = 1 << pt;
        bool c1 = (lane >> (pc - 5)) & 1;
#pragma unroll
        for (int m = 0; m < 32; ++m) {
            if (!(m & tm)) {
                float2 a = st[m], b = st[m | tm];
                st[m]      = c1 ? b : a;
                st[m | tm] = c1 ? a : b;
            }
        }
    } else {
        // lane control, lane target: indexed shuffle (swap among c=1 lanes)
        constexpr int tlm = 1 << (pt - 5);
        int src = ((lane >> (pc - 5)) & 1) ? (lane ^ tlm) : lane;
#pragma unroll
        for (int m = 0; m < 32; ++m) st[m] = shidx2(st[m], src);
    }
}

// ---------------------------------------------------------------------------
// Sequencers (compile-time unrolled over wires)
// ---------------------------------------------------------------------------
template <int W>
__device__ __forceinline__ void rotSeq(float2 st[32], int lane, int gbase) {
    rotGate<W>(st, lane, gbase + W);
    if constexpr (W < NW - 1) rotSeq<W + 1>(st, lane, gbase);
}
template <int R, int W>
__device__ __forceinline__ void cnotSeq(float2 st[32], int lane) {
    cnotGate<W, (W + R) % NW>(st, lane);
    if constexpr (W < NW - 1) cnotSeq<R, W + 1>(st, lane);
}
template <int W>
__device__ __forceinline__ void rySeq(float2 st[32], int lane, float x) {
    float xv = __shfl_sync(FULL, x, W);
    float s, c;
    sincosf(xv * 0.78539816339744831f, &s, &c);  // theta/2 = x * pi/4
    ryGate<W>(st, lane, c, s);
    if constexpr (W < NW - 1) rySeq<W + 1>(st, lane, x);
}

// ---------------------------------------------------------------------------
// Main kernel: one warp per sample; full 1024-amp state in registers.
// ---------------------------------------------------------------------------
__global__ void __launch_bounds__(128, 4)
vqc_kernel(const float* __restrict__ X, const float* __restrict__ bias,
           float* __restrict__ out, int B) {
    int warp = (blockIdx.x * blockDim.x + threadIdx.x) >> 5;
    int lane = threadIdx.x & 31;
    if (warp >= B) return;

    float x = (lane < NW) ? X[warp * NW + lane] : 0.0f;

    float2 st[32];
#pragma unroll
    for (int m = 0; m < 32; ++m) st[m] = make_float2(0.0f, 0.0f);
    st[0].x = (lane == 0) ? 1.0f : 0.0f;

    // Angle encoding: RY(x_w * pi/2) on each wire
    rySeq<0>(st, lane, x);

    // StronglyEntanglingLayers
#pragma unroll 1
    for (int l = 0; l < NL; ++l) {
        rotSeq<0>(st, lane, l * NW);
        switch (l) {
            case 0: cnotSeq<1, 0>(st, lane); break;
            case 1: cnotSeq<2, 0>(st, lane); break;
            case 2: cnotSeq<3, 0>(st, lane); break;
            default: cnotSeq<4, 0>(st, lane); break;
        }
    }

    // <Z> on wire 9 (index bit 0 = local bit 0)
    float z = 0.0f;
#pragma unroll
    for (int m = 0; m < 32; ++m) {
        float p = fmaf(st[m].x, st[m].x, st[m].y * st[m].y);
        z = (m & 1) ? (z - p) : (z + p);
    }
#pragma unroll
    for (int o = 16; o; o >>= 1) z += __shfl_xor_sync(FULL, z, o);
    if (lane == 0) out[warp] = z + bias[0];
}

// ---------------------------------------------------------------------------
extern "C" void kernel_launch(void* const* d_in, const int* in_sizes, int n_in,
                              void* d_out, int out_size) {
    const float* X = (const float*)d_in[0];
    const float* w = (const float*)d_in[1];
    const float* bias = (const float*)d_in[2];
    float* out = (float*)d_out;

    int B = in_sizes[0] / NW;

    prep_kernel<<<1, 64>>>(w);

    int warpsPerBlock = 4;  // blockDim 128
    int blocks = (B + warpsPerBlock - 1) / warpsPerBlock;
    vqc_kernel<<<blocks, 128>>>(X, bias, out, B);
}

// round 2
// speedup vs baseline: 1.3963x; 1.3963x over previous
#include <cuda_runtime.h>

#define FULL 0xffffffffu
constexpr int NW = 10;   // wires
constexpr int NL = 4;    // layers

// Per Rot gate: 2 x float4 = (U00.re,U00.im,U01.re,U01.im), (U10.re,U10.im,U11.re,U11.im)
__device__ float4 g_rot[NL * NW * 2];

// ---------------------------------------------------------------------------
// Prep: build the 40 Rot matrices from weights (shared across all samples)
// ---------------------------------------------------------------------------
__global__ void prep_kernel(const float* __restrict__ w) {
    int g = blockIdx.x * blockDim.x + threadIdx.x;
    if (g >= NL * NW) return;
    float phi = w[g * 3 + 0], th = w[g * 3 + 1], om = w[g * 3 + 2];
    float sth, cth;
    sincosf(0.5f * th, &sth, &cth);
    float sp, cp;  // e^{-i(phi+om)/2}
    sincosf(-0.5f * (phi + om), &sp, &cp);
    float sm, cm;  // e^{+i(phi-om)/2}
    sincosf(0.5f * (phi - om), &sm, &cm);
    g_rot[g * 2 + 0] = make_float4(cp * cth, sp * cth, -cm * sth, -sm * sth);
    g_rot[g * 2 + 1] = make_float4(cm * sth, -sm * sth, cp * cth, -sp * cth);
}

// ---------------------------------------------------------------------------
// Packed f32x2 helpers (SoA over amplitude bit 0: each float2 holds the same
// component of two adjacent amplitudes)
// ---------------------------------------------------------------------------
__device__ __forceinline__ float2 f2fma(float2 a, float2 b, float2 c) {
    float2 d;
    asm("{\n\t"
        ".reg .b64 ra, rb, rc, rd;\n\t"
        "mov.b64 ra, {%2, %3};\n\t"
        "mov.b64 rb, {%4, %5};\n\t"
        "mov.b64 rc, {%6, %7};\n\t"
        "fma.rn.f32x2 rd, ra, rb, rc;\n\t"
        "mov.b64 {%0, %1}, rd;\n\t"
        "}"
        : "=f"(d.x), "=f"(d.y)
        : "f"(a.x), "f"(a.y), "f"(b.x), "f"(b.y), "f"(c.x), "f"(c.y));
    return d;
}
__device__ __forceinline__ float2 f2mul(float2 a, float2 b) {
    float2 d;
    asm("{\n\t"
        ".reg .b64 ra, rb, rd;\n\t"
        "mov.b64 ra, {%2, %3};\n\t"
        "mov.b64 rb, {%4, %5};\n\t"
        "mul.rn.f32x2 rd, ra, rb;\n\t"
        "mov.b64 {%0, %1}, rd;\n\t"
        "}"
        : "=f"(d.x), "=f"(d.y)
        : "f"(a.x), "f"(a.y), "f"(b.x), "f"(b.y));
    return d;
}
__device__ __forceinline__ float2 pk(float v) { return make_float2(v, v); }

__device__ __forceinline__ float2 shx2(float2 v, int mask) {
    float2 r;
    r.x = __shfl_xor_sync(FULL, v.x, mask);
    r.y = __shfl_xor_sync(FULL, v.y, mask);
    return r;
}
__device__ __forceinline__ float2 shidx2(float2 v, int src) {
    float2 r;
    r.x = __shfl_sync(FULL, v.x, src);
    r.y = __shfl_sync(FULL, v.y, src);
    return r;
}
__device__ __forceinline__ float2 cmul(float2 u, float2 a) {
    return make_float2(u.x * a.x - u.y * a.y, u.x * a.y + u.y * a.x);
}
__device__ __forceinline__ float2 cmadd(float2 u, float2 a, float2 acc) {
    acc.x = fmaf(u.x, a.x, fmaf(-u.y, a.y, acc.x));
    acc.y = fmaf(u.x, a.y, fmaf(u.y, a.x, acc.y));
    return acc;
}

// ---------------------------------------------------------------------------
// Layout: amplitude index bit for wire W is p = 9 - W.
//   bits 9..5  -> lane bits (lane bit p-5)
//   bits 4..1  -> packed-register index k (k bit p-1)
//   bit  0     -> half within packed float2 (.x = bit0==0, .y = bit0==1)
// State: RE[16], IM[16] (float2 each, SoA packed over bit 0).
// ---------------------------------------------------------------------------

template <int W>
__device__ __forceinline__ void rotGate(float2 RE[16], float2 IM[16], int lane, int gidx) {
    float4 g0 = g_rot[gidx * 2 + 0];
    float4 g1 = g_rot[gidx * 2 + 1];
    float2 U00 = make_float2(g0.x, g0.y), U01 = make_float2(g0.z, g0.w);
    float2 U10 = make_float2(g1.x, g1.y), U11 = make_float2(g1.z, g1.w);
    constexpr int p = 9 - W;
    if constexpr (p >= 5) {
        constexpr int lb = p - 5;
        int bit = (lane >> lb) & 1;
        float2 co = bit ? U11 : U00;  // coeff for own amplitude
        float2 ct = bit ? U10 : U01;  // coeff for partner amplitude
        const float2 cox = pk(co.x), coy = pk(co.y), ncoy = pk(-co.y);
        const float2 ctx = pk(ct.x), cty = pk(ct.y), ncty = pk(-ct.y);
#pragma unroll
        for (int k = 0; k < 16; ++k) {
            float2 ore = shx2(RE[k], 1 << lb);
            float2 oim = shx2(IM[k], 1 << lb);
            float2 nre = f2fma(ncty, oim, f2fma(ctx, ore, f2fma(ncoy, IM[k], f2mul(cox, RE[k]))));
            float2 nim = f2fma(cty, ore, f2fma(ctx, oim, f2fma(coy, RE[k], f2mul(cox, IM[k]))));
            RE[k] = nre; IM[k] = nim;
        }
    } else if constexpr (p >= 1) {
        constexpr int kb = 1 << (p - 1);
        const float2 u00x = pk(U00.x), u00y = pk(U00.y), nu00y = pk(-U00.y);
        const float2 u01x = pk(U01.x), u01y = pk(U01.y), nu01y = pk(-U01.y);
        const float2 u10x = pk(U10.x), u10y = pk(U10.y), nu10y = pk(-U10.y);
        const float2 u11x = pk(U11.x), u11y = pk(U11.y), nu11y = pk(-U11.y);
#pragma unroll
        for (int k = 0; k < 16; ++k) {
            if (!(k & kb)) {
                const int j = k | kb;
                float2 a0re = RE[k], a0im = IM[k], a1re = RE[j], a1im = IM[j];
                RE[k] = f2fma(nu01y, a1im, f2fma(u01x, a1re, f2fma(nu00y, a0im, f2mul(u00x, a0re))));
                IM[k] = f2fma(u01y, a1re, f2fma(u01x, a1im, f2fma(u00y, a0re, f2mul(u00x, a0im))));
                RE[j] = f2fma(nu11y, a1im, f2fma(u11x, a1re, f2fma(nu10y, a0im, f2mul(u10x, a0re))));
                IM[j] = f2fma(u11y, a1re, f2fma(u11x, a1im, f2fma(u10y, a0re, f2mul(u10x, a0im))));
            }
        }
    } else {
        // p == 0: butterfly between the two halves of each packed register
#pragma unroll
        for (int k = 0; k < 16; ++k) {
            float2 a0 = make_float2(RE[k].x, IM[k].x);
            float2 a1 = make_float2(RE[k].y, IM[k].y);
            float2 n0 = cmadd(U01, a1, cmul(U00, a0));
            float2 n1 = cmadd(U11, a1, cmul(U10, a0));
            RE[k] = make_float2(n0.x, n1.x);
            IM[k] = make_float2(n0.y, n1.y);
        }
    }
}

template <int W>
__device__ __forceinline__ void ryGate(float2 RE[16], float2 IM[16], int lane, float c, float s) {
    constexpr int p = 9 - W;
    if constexpr (p >= 5) {
        constexpr int lb = p - 5;
        int bit = (lane >> lb) & 1;
        float sg = bit ? s : -s;  // new = c*own + sg*other
        const float2 cp = pk(c), sp = pk(sg);
#pragma unroll
        for (int k = 0; k < 16; ++k) {
            float2 ore = shx2(RE[k], 1 << lb);
            float2 oim = shx2(IM[k], 1 << lb);
            RE[k] = f2fma(cp, RE[k], f2mul(sp, ore));
            IM[k] = f2fma(cp, IM[k], f2mul(sp, oim));
        }
    } else if constexpr (p >= 1) {
        constexpr int kb = 1 << (p - 1);
        const float2 cp = pk(c), sp = pk(s), np = pk(-s);
#pragma unroll
        for (int k = 0; k < 16; ++k) {
            if (!(k & kb)) {
                const int j = k | kb;
                float2 a0re = RE[k], a0im = IM[k], a1re = RE[j], a1im = IM[j];
                RE[k] = f2fma(cp, a0re, f2mul(np, a1re));
                IM[k] = f2fma(cp, a0im, f2mul(np, a1im));
                RE[j] = f2fma(cp, a1re, f2mul(sp, a0re));
                IM[j] = f2fma(cp, a1im, f2mul(sp, a0im));
            }
        }
    } else {
        // p == 0: scalar within-pack butterfly
#pragma unroll
        for (int k = 0; k < 16; ++k) {
            float rx = RE[k].x, ry = RE[k].y;
            float ix = IM[k].x, iy = IM[k].y;
            RE[k] = make_float2(fmaf(c, rx, -s * ry), fmaf(s, rx, c * ry));
            IM[k] = make_float2(fmaf(c, ix, -s * iy), fmaf(s, ix, c * iy));
        }
    }
}

// ---------------------------------------------------------------------------
// CNOT (non lane-lane cases; lane-lane blocks are composed per layer)
// ---------------------------------------------------------------------------
template <int CW, int TW>
__device__ __forceinline__ void cnotGate(float2 RE[16], float2 IM[16], int lane) {
    constexpr int pc = 9 - CW, pt = 9 - TW;
    if constexpr (pc >= 1 && pc <= 4 && pt >= 1 && pt <= 4) {
        // local-local: register swap
        constexpr int cm = 1 << (pc - 1), tm = 1 << (pt - 1);
#pragma unroll
        for (int k = 0; k < 16; ++k) {
            if ((k & cm) && !(k & tm)) {
                float2 a = RE[k]; RE[k] = RE[k | tm]; RE[k | tm] = a;
                float2 b = IM[k]; IM[k] = IM[k | tm]; IM[k | tm] = b;
            }
        }
    } else if constexpr (pc >= 1 && pc <= 4 && pt >= 5) {
        // local control, lane target
        constexpr int cm = 1 << (pc - 1), tlm = 1 << (pt - 5);
#pragma unroll
        for (int k = 0; k < 16; ++k) {
            if (k & cm) { RE[k] = shx2(RE[k], tlm); IM[k] = shx2(IM[k], tlm); }
        }
    } else if constexpr (pc >= 1 && pc <= 4 && pt == 0) {
        // local control, packed-bit target: swap halves where control set
        constexpr int cm = 1 << (pc - 1);
#pragma unroll
        for (int k = 0; k < 16; ++k) {
            if (k & cm) {
                RE[k] = make_float2(RE[k].y, RE[k].x);
                IM[k] = make_float2(IM[k].y, IM[k].x);
            }
        }
    } else if constexpr (pc >= 5 && pt >= 1 && pt <= 4) {
        // lane control, local target: predicated register swap
        constexpr int tm = 1 << (pt - 1);
        bool c1 = (lane >> (pc - 5)) & 1;
#pragma unroll
        for (int k = 0; k < 16; ++k) {
            if (!(k & tm)) {
                float2 a = RE[k], b = RE[k | tm];
                RE[k] = c1 ? b : a; RE[k | tm] = c1 ? a : b;
                float2 e = IM[k], f = IM[k | tm];
                IM[k] = c1 ? f : e; IM[k | tm] = c1 ? e : f;
            }
        }
    } else if constexpr (pc >= 5 && pt == 0) {
        // lane control, packed-bit target: predicated within-pack half swap
        bool c1 = (lane >> (pc - 5)) & 1;
#pragma unroll
        for (int k = 0; k < 16; ++k) {
            float2 a = RE[k], b = IM[k];
            RE[k] = c1 ? make_float2(a.y, a.x) : a;
            IM[k] = c1 ? make_float2(b.y, b.x) : b;
        }
    } else if constexpr (pc == 0 && pt >= 5) {
        // packed-bit control, lane target: only .y halves move (1 SHFL each)
        constexpr int tlm = 1 << (pt - 5);
#pragma unroll
        for (int k = 0; k < 16; ++k) {
            RE[k].y = __shfl_xor_sync(FULL, RE[k].y, tlm);
            IM[k].y = __shfl_xor_sync(FULL, IM[k].y, tlm);
        }
    } else if constexpr (pc == 0 && pt >= 1 && pt <= 4) {
        // packed-bit control, local target: swap .y halves across register pair
        constexpr int tm = 1 << (pt - 1);
#pragma unroll
        for (int k = 0; k < 16; ++k) {
            if (!(k & tm)) {
                float t = RE[k].y; RE[k].y = RE[k | tm].y; RE[k | tm].y = t;
                float u = IM[k].y; IM[k].y = IM[k | tm].y; IM[k | tm].y = u;
            }
        }
    } else {
        // lane-lane fallback (not used; composed path handles these)
        constexpr int tlm = 1 << (pt - 5);
        int src = ((lane >> (pc - 5)) & 1) ? (lane ^ tlm) : lane;
#pragma unroll
        for (int k = 0; k < 16; ++k) { RE[k] = shidx2(RE[k], src); IM[k] = shidx2(IM[k], src); }
    }
}

// ---------------------------------------------------------------------------
// Sequencers
// ---------------------------------------------------------------------------
template <int W>
__device__ __forceinline__ void rotSeq(float2 RE[16], float2 IM[16], int lane, int gbase) {
    rotGate<W>(RE, IM, lane, gbase + W);
    if constexpr (W < NW - 1) rotSeq<W + 1>(RE, IM, lane, gbase);
}

template <int R, int W>
__device__ __forceinline__ void cnotRest(float2 RE[16], float2 IM[16], int lane) {
    cnotGate<W, (W + R) % NW>(RE, IM, lane);
    if constexpr (W < NW - 1) cnotRest<R, W + 1>(RE, IM, lane);
}

// Layer R: CNOT(w, (w+R)%10) for w=0..9. The leading w=0..(4-R) block is
// lane-lane only -> compose into ONE indexed shuffle pass (linear map on
// lane bits over GF(2)); remaining gates go through cnotGate.
template <int R>
__device__ __forceinline__ void cnotLayer(float2 RE[16], float2 IM[16], int lane) {
    // gather src: final[i] = init[f_first(...f_last(i)...)] ; evaluate last
    // gate's map first. Gate w: control lane-bit 4-w, target lane-bit 4-w-R.
    int src = lane;
#pragma unroll
    for (int w = 4 - R; w >= 0; --w) {
        int cb = 4 - w, tb = 4 - w - R;
        src ^= (((src >> cb) & 1) << tb);
    }
#pragma unroll
    for (int k = 0; k < 16; ++k) { RE[k] = shidx2(RE[k], src); IM[k] = shidx2(IM[k], src); }
    cnotRest<R, 5 - R>(RE, IM, lane);
}

template <int W>
__device__ __forceinline__ void rySeq(float2 RE[16], float2 IM[16], int lane, float x) {
    float xv = __shfl_sync(FULL, x, W);
    float s, c;
    sincosf(xv * 0.78539816339744831f, &s, &c);  // theta/2 = x * pi/4
    ryGate<W>(RE, IM, lane, c, s);
    if constexpr (W < NW - 1) rySeq<W + 1>(RE, IM, lane, x);
}

// ---------------------------------------------------------------------------
// Main kernel: one warp per sample; 1024-amp state in registers (SoA packed).
// ---------------------------------------------------------------------------
__global__ void __launch_bounds__(128, 4)
vqc_kernel(const float* __restrict__ X, const float* __restrict__ bias,
           float* __restrict__ out, int B) {
    int warp = (blockIdx.x * blockDim.x + threadIdx.x) >> 5;
    int lane = threadIdx.x & 31;
    if (warp >= B) return;

    float x = (lane < NW) ? X[warp * NW + lane] : 0.0f;

    float2 RE[16], IM[16];
#pragma unroll
    for (int k = 0; k < 16; ++k) { RE[k] = make_float2(0.f, 0.f); IM[k] = make_float2(0.f, 0.f); }
    RE[0].x = (lane == 0) ? 1.0f : 0.0f;

    // Angle encoding: RY(x_w * pi/2)
    rySeq<0>(RE, IM, lane, x);

    // StronglyEntanglingLayers
#pragma unroll 1
    for (int l = 0; l < NL; ++l) {
        rotSeq<0>(RE, IM, lane, l * NW);
        switch (l) {
            case 0:  cnotLayer<1>(RE, IM, lane); break;
            case 1:  cnotLayer<2>(RE, IM, lane); break;
            case 2:  cnotLayer<3>(RE, IM, lane); break;
            default: cnotLayer<4>(RE, IM, lane); break;
        }
    }

    // <Z> on wire 9 (bit 0 = packed half): acc.x = P(0), acc.y = P(1)
    float2 acc = make_float2(0.f, 0.f);
#pragma unroll
    for (int k = 0; k < 16; ++k)
        acc = f2fma(RE[k], RE[k], f2fma(IM[k], IM[k], acc));
    float z = acc.x - acc.y;
#pragma unroll
    for (int o = 16; o; o >>= 1) z += __shfl_xor_sync(FULL, z, o);
    if (lane == 0) out[warp] = z + bias[0];
}

// ---------------------------------------------------------------------------
extern "C" void kernel_launch(void* const* d_in, const int* in_sizes, int n_in,
                              void* d_out, int out_size) {
    const float* X = (const float*)d_in[0];
    const float* w = (const float*)d_in[1];
    const float* bias = (const float*)d_in[2];
    float* out = (float*)d_out;

    int B = in_sizes[0] / NW;

    prep_kernel<<<1, 64>>>(w);

    int blocks = (B + 3) / 4;  // 4 warps per 128-thread block
    vqc_kernel<<<blocks, 128>>>(X, bias, out, B);
}

// round 3
// speedup vs baseline: 1.8249x; 1.3070x over previous
#include <cuda_runtime.h>

#define FULL 0xffffffffu
constexpr int NW = 10;   // wires
constexpr int NL = 4;    // layers

// Per Rot gate: 2 x float4 = (U00.re,U00.im,U01.re,U01.im), (U10.re,U10.im,U11.re,U11.im)
__device__ float4 g_rot[NL * NW * 2];

// ---------------------------------------------------------------------------
// Prep: build the 40 Rot matrices from weights
// ---------------------------------------------------------------------------
__global__ void prep_kernel(const float* __restrict__ w) {
    int g = blockIdx.x * blockDim.x + threadIdx.x;
    if (g >= NL * NW) return;
    float phi = w[g * 3 + 0], th = w[g * 3 + 1], om = w[g * 3 + 2];
    float sth, cth;
    sincosf(0.5f * th, &sth, &cth);
    float sp, cp;  // e^{-i(phi+om)/2}
    sincosf(-0.5f * (phi + om), &sp, &cp);
    float sm, cm;  // e^{+i(phi-om)/2}
    sincosf(0.5f * (phi - om), &sm, &cm);
    g_rot[g * 2 + 0] = make_float4(cp * cth, sp * cth, -cm * sth, -sm * sth);
    g_rot[g * 2 + 1] = make_float4(cm * sth, -sm * sth, cp * cth, -sp * cth);
}

// ---------------------------------------------------------------------------
// Packed f32x2 helpers
// ---------------------------------------------------------------------------
__device__ __forceinline__ float2 f2fma(float2 a, float2 b, float2 c) {
    float2 d;
    asm("{\n\t"
        ".reg .b64 ra, rb, rc, rd;\n\t"
        "mov.b64 ra, {%2, %3};\n\t"
        "mov.b64 rb, {%4, %5};\n\t"
        "mov.b64 rc, {%6, %7};\n\t"
        "fma.rn.f32x2 rd, ra, rb, rc;\n\t"
        "mov.b64 {%0, %1}, rd;\n\t"
        "}"
        : "=f"(d.x), "=f"(d.y)
        : "f"(a.x), "f"(a.y), "f"(b.x), "f"(b.y), "f"(c.x), "f"(c.y));
    return d;
}
__device__ __forceinline__ float2 f2mul(float2 a, float2 b) {
    float2 d;
    asm("{\n\t"
        ".reg .b64 ra, rb, rd;\n\t"
        "mov.b64 ra, {%2, %3};\n\t"
        "mov.b64 rb, {%4, %5};\n\t"
        "mul.rn.f32x2 rd, ra, rb;\n\t"
        "mov.b64 {%0, %1}, rd;\n\t"
        "}"
        : "=f"(d.x), "=f"(d.y)
        : "f"(a.x), "f"(a.y), "f"(b.x), "f"(b.y));
    return d;
}
__device__ __forceinline__ float2 pk(float v) { return make_float2(v, v); }

__device__ __forceinline__ float2 shx2(float2 v, int mask) {
    float2 r;
    r.x = __shfl_xor_sync(FULL, v.x, mask);
    r.y = __shfl_xor_sync(FULL, v.y, mask);
    return r;
}
__device__ __forceinline__ float2 shidx2(float2 v, int src) {
    float2 r;
    r.x = __shfl_sync(FULL, v.x, src);
    r.y = __shfl_sync(FULL, v.y, src);
    return r;
}

// ---------------------------------------------------------------------------
// Layout: amplitude index bit for wire W is p = 9 - W.
//   bits 9..5 -> lane bits (lane bit p-5)
//   bits 4..1 -> register index bits (k bit p-1)
//   bit  0    -> half within packed float2
// State: RE[16], IM[16] (SoA packed over bit 0).
// ---------------------------------------------------------------------------

// Apply a general complex 2x2 (U00,U01,U10,U11 as float2(re,im)) on wire W.
template <int W>
__device__ __forceinline__ void applyMat(float2 RE[16], float2 IM[16], int lane,
                                         float2 U00, float2 U01, float2 U10, float2 U11) {
    constexpr int p = 9 - W;
    if constexpr (p >= 5) {
        constexpr int lb = p - 5;
        int bit = (lane >> lb) & 1;
        float2 co = bit ? U11 : U00;  // coeff for own amplitude
        float2 ct = bit ? U10 : U01;  // coeff for partner amplitude
        const float2 cox = pk(co.x), coy = pk(co.y), ncoy = pk(-co.y);
        const float2 ctx = pk(ct.x), cty = pk(ct.y), ncty = pk(-ct.y);
#pragma unroll
        for (int k = 0; k < 16; ++k) {
            float2 ore = shx2(RE[k], 1 << lb);
            float2 oim = shx2(IM[k], 1 << lb);
            float2 nre = f2fma(ncty, oim, f2fma(ctx, ore, f2fma(ncoy, IM[k], f2mul(cox, RE[k]))));
            float2 nim = f2fma(cty, ore, f2fma(ctx, oim, f2fma(coy, RE[k], f2mul(cox, IM[k]))));
            RE[k] = nre; IM[k] = nim;
        }
    } else if constexpr (p >= 1) {
        constexpr int kb = 1 << (p - 1);
        const float2 u00x = pk(U00.x), u00y = pk(U00.y), nu00y = pk(-U00.y);
        const float2 u01x = pk(U01.x), u01y = pk(U01.y), nu01y = pk(-U01.y);
        const float2 u10x = pk(U10.x), u10y = pk(U10.y), nu10y = pk(-U10.y);
        const float2 u11x = pk(U11.x), u11y = pk(U11.y), nu11y = pk(-U11.y);
#pragma unroll
        for (int k = 0; k < 16; ++k) {
            if (!(k & kb)) {
                const int j = k | kb;
                float2 a0re = RE[k], a0im = IM[k], a1re = RE[j], a1im = IM[j];
                RE[k] = f2fma(nu01y, a1im, f2fma(u01x, a1re, f2fma(nu00y, a0im, f2mul(u00x, a0re))));
                IM[k] = f2fma(u01y, a1re, f2fma(u01x, a1im, f2fma(u00y, a0re, f2mul(u00x, a0im))));
                RE[j] = f2fma(nu11y, a1im, f2fma(u11x, a1re, f2fma(nu10y, a0im, f2mul(u10x, a0re))));
                IM[j] = f2fma(u11y, a1re, f2fma(u11x, a1im, f2fma(u10y, a0re, f2mul(u10x, a0im))));
            }
        }
    } else {
        // p == 0: halves pair within each register; pack rows (U00|U10) per half
        const float2 c00x = make_float2(U00.x, U10.x), c00y = make_float2(U00.y, U10.y);
        const float2 c01x = make_float2(U01.x, U11.x), c01y = make_float2(U01.y, U11.y);
        const float2 n00y = make_float2(-U00.y, -U10.y), n01y = make_float2(-U01.y, -U11.y);
#pragma unroll
        for (int k = 0; k < 16; ++k) {
            float a0r = RE[k].x, a0i = IM[k].x, a1r = RE[k].y, a1i = IM[k].y;
            float2 nre = f2fma(n01y, pk(a1i), f2fma(c01x, pk(a1r),
                          f2fma(n00y, pk(a0i), f2mul(c00x, pk(a0r)))));
            float2 nim = f2fma(c01y, pk(a1r), f2fma(c01x, pk(a1i),
                          f2fma(c00y, pk(a0r), f2mul(c00x, pk(a0i)))));
            RE[k] = nre; IM[k] = nim;
        }
    }
}

// ---------------------------------------------------------------------------
// CNOT cases
// ---------------------------------------------------------------------------
template <int CW, int TW>
__device__ __forceinline__ void cnotGate(float2 RE[16], float2 IM[16], int lane) {
    constexpr int pc = 9 - CW, pt = 9 - TW;
    if constexpr (pc >= 1 && pc <= 4 && pt >= 1 && pt <= 4) {
        constexpr int cm = 1 << (pc - 1), tm = 1 << (pt - 1);
#pragma unroll
        for (int k = 0; k < 16; ++k) {
            if ((k & cm) && !(k & tm)) {
                float2 a = RE[k]; RE[k] = RE[k | tm]; RE[k | tm] = a;
                float2 b = IM[k]; IM[k] = IM[k | tm]; IM[k | tm] = b;
            }
        }
    } else if constexpr (pc >= 1 && pc <= 4 && pt >= 5) {
        constexpr int cm = 1 << (pc - 1), tlm = 1 << (pt - 5);
#pragma unroll
        for (int k = 0; k < 16; ++k) {
            if (k & cm) { RE[k] = shx2(RE[k], tlm); IM[k] = shx2(IM[k], tlm); }
        }
    } else if constexpr (pc >= 1 && pc <= 4 && pt == 0) {
        constexpr int cm = 1 << (pc - 1);
#pragma unroll
        for (int k = 0; k < 16; ++k) {
            if (k & cm) {
                RE[k] = make_float2(RE[k].y, RE[k].x);
                IM[k] = make_float2(IM[k].y, IM[k].x);
            }
        }
    } else if constexpr (pc >= 5 && pt >= 1 && pt <= 4) {
        constexpr int tm = 1 << (pt - 1);
        bool c1 = (lane >> (pc - 5)) & 1;
#pragma unroll
        for (int k = 0; k < 16; ++k) {
            if (!(k & tm)) {
                float2 a = RE[k], b = RE[k | tm];
                RE[k] = c1 ? b : a; RE[k | tm] = c1 ? a : b;
                float2 e = IM[k], f = IM[k | tm];
                IM[k] = c1 ? f : e; IM[k | tm] = c1 ? e : f;
            }
        }
    } else if constexpr (pc >= 5 && pt == 0) {
        bool c1 = (lane >> (pc - 5)) & 1;
#pragma unroll
        for (int k = 0; k < 16; ++k) {
            float2 a = RE[k], b = IM[k];
            RE[k] = c1 ? make_float2(a.y, a.x) : a;
            IM[k] = c1 ? make_float2(b.y, b.x) : b;
        }
    } else if constexpr (pc == 0 && pt >= 5) {
        constexpr int tlm = 1 << (pt - 5);
#pragma unroll
        for (int k = 0; k < 16; ++k) {
            RE[k].y = __shfl_xor_sync(FULL, RE[k].y, tlm);
            IM[k].y = __shfl_xor_sync(FULL, IM[k].y, tlm);
        }
    } else if constexpr (pc == 0 && pt >= 1 && pt <= 4) {
        constexpr int tm = 1 << (pt - 1);
#pragma unroll
        for (int k = 0; k < 16; ++k) {
            if (!(k & tm)) {
                float t = RE[k].y; RE[k].y = RE[k | tm].y; RE[k | tm].y = t;
                float u = IM[k].y; IM[k].y = IM[k | tm].y; IM[k | tm].y = u;
            }
        }
    } else {
        constexpr int tlm = 1 << (pt - 5);
        int src = ((lane >> (pc - 5)) & 1) ? (lane ^ tlm) : lane;
#pragma unroll
        for (int k = 0; k < 16; ++k) { RE[k] = shidx2(RE[k], src); IM[k] = shidx2(IM[k], src); }
    }
}

// ---------------------------------------------------------------------------
// Sequencers
// ---------------------------------------------------------------------------
template <int W>
__device__ __forceinline__ void rotSeq(float2 RE[16], float2 IM[16], int lane, int gbase) {
    int gidx = gbase + W;
    float4 g0 = g_rot[gidx * 2 + 0];
    float4 g1 = g_rot[gidx * 2 + 1];
    applyMat<W>(RE, IM, lane,
                make_float2(g0.x, g0.y), make_float2(g0.z, g0.w),
                make_float2(g1.x, g1.y), make_float2(g1.z, g1.w));
    if constexpr (W < NW - 1) rotSeq<W + 1>(RE, IM, lane, gbase);
}

// Fused layer-1: F = Rot(0,w) * RY(x_w * pi/2). c,s broadcast from lane w.
template <int W>
__device__ __forceinline__ void fusedSeq(float2 RE[16], float2 IM[16], int lane,
                                         float myc, float mys) {
    float cw = __shfl_sync(FULL, myc, W);
    float sw = __shfl_sync(FULL, mys, W);
    float4 g0 = g_rot[W * 2 + 0];
    float4 g1 = g_rot[W * 2 + 1];
    float2 U00 = make_float2(g0.x, g0.y), U01 = make_float2(g0.z, g0.w);
    float2 U10 = make_float2(g1.x, g1.y), U11 = make_float2(g1.z, g1.w);
    // F = U * [[c,-s],[s,c]]
    float2 F00 = make_float2(fmaf(U00.x, cw, U01.x * sw), fmaf(U00.y, cw, U01.y * sw));
    float2 F01 = make_float2(fmaf(U01.x, cw, -U00.x * sw), fmaf(U01.y, cw, -U00.y * sw));
    float2 F10 = make_float2(fmaf(U10.x, cw, U11.x * sw), fmaf(U10.y, cw, U11.y * sw));
    float2 F11 = make_float2(fmaf(U11.x, cw, -U10.x * sw), fmaf(U11.y, cw, -U10.y * sw));
    applyMat<W>(RE, IM, lane, F00, F01, F10, F11);
    if constexpr (W < NW - 1) fusedSeq<W + 1>(RE, IM, lane, myc, mys);
}

template <int R, int W>
__device__ __forceinline__ void cnotRest(float2 RE[16], float2 IM[16], int lane) {
    cnotGate<W, (W + R) % NW>(RE, IM, lane);
    if constexpr (W < NW - 1) cnotRest<R, W + 1>(RE, IM, lane);
}

// Ring R: leading lane-lane block composed into ONE indexed-shuffle pass.
template <int R>
__device__ __forceinline__ void cnotLayer(float2 RE[16], float2 IM[16], int lane) {
    int src = lane;
#pragma unroll
    for (int w = 4 - R; w >= 0; --w) {
        int cb = 4 - w, tb = 4 - w - R;
        src ^= (((src >> cb) & 1) << tb);
    }
#pragma unroll
    for (int k = 0; k < 16; ++k) { RE[k] = shidx2(RE[k], src); IM[k] = shidx2(IM[k], src); }
    cnotRest<R, 5 - R>(RE, IM, lane);
}

// ---------------------------------------------------------------------------
// Main kernel
// ---------------------------------------------------------------------------
__global__ void __launch_bounds__(128, 4)
vqc_kernel(const float* __restrict__ X, const float* __restrict__ bias,
           float* __restrict__ out, int B) {
    int warp = (blockIdx.x * blockDim.x + threadIdx.x) >> 5;
    int lane = threadIdx.x & 31;
    if (warp >= B) return;

    float x = (lane < NW) ? X[warp * NW + lane] : 0.0f;
    float mys, myc;
    sincosf(x * 0.78539816339744831f, &mys, &myc);  // theta/2 = x * pi/4

    float2 RE[16], IM[16];
#pragma unroll
    for (int k = 0; k < 16; ++k) { RE[k] = make_float2(0.f, 0.f); IM[k] = make_float2(0.f, 0.f); }
    RE[0].x = (lane == 0) ? 1.0f : 0.0f;

    // Layer 1: RY encoding fused into Rot, then ring r=1
    fusedSeq<0>(RE, IM, lane, myc, mys);
    cnotLayer<1>(RE, IM, lane);

    // Layers 2-4 (ring 4 deferred into measurement mask)
#pragma unroll 1
    for (int l = 1; l < NL; ++l) {
        rotSeq<0>(RE, IM, lane, l * NW);
        switch (l) {
            case 1: cnotLayer<2>(RE, IM, lane); break;
            case 2: cnotLayer<3>(RE, IM, lane); break;
            default: break;  // ring 4 deferred
        }
    }

    // Measurement: Z on wire 9 through deferred ring-4 => parity mask
    // m_v = bit0 ^ bit4 ^ bit8 = half ^ k_bit3 ^ lane_bit3
    float2 accA = make_float2(0.f, 0.f);  // k < 8
    float2 accB = make_float2(0.f, 0.f);  // k >= 8
#pragma unroll
    for (int k = 0; k < 8; ++k)
        accA = f2fma(RE[k], RE[k], f2fma(IM[k], IM[k], accA));
#pragma unroll
    for (int k = 8; k < 16; ++k)
        accB = f2fma(RE[k], RE[k], f2fma(IM[k], IM[k], accB));
    float z = (accA.x - accA.y) - (accB.x - accB.y);
    if ((lane >> 3) & 1) z = -z;
#pragma unroll
    for (int o = 16; o; o >>= 1) z += __shfl_xor_sync(FULL, z, o);
    if (lane == 0) out[warp] = z + bias[0];
}

// ---------------------------------------------------------------------------
extern "C" void kernel_launch(void* const* d_in, const int* in_sizes, int n_in,
                              void* d_out, int out_size) {
    const float* X = (const float*)d_in[0];
    const float* w = (const float*)d_in[1];
    const float* bias = (const float*)d_in[2];
    float* out = (float*)d_out;

    int B = in_sizes[0] / NW;

    prep_kernel<<<1, 64>>>(w);

    int blocks = (B + 3) / 4;  // 4 warps per 128-thread block
    vqc_kernel<<<blocks, 128>>>(X, bias, out, B);
}